// round 3
// baseline (speedup 1.0000x reference)
#include <cuda_runtime.h>
#include <cstdint>

#define N_NODES 50000
#define N_EDGES 800000

// ---------------- device scratch (allocation-free rule: __device__ globals) ----
__device__ __align__(16) float g_dinv[N_NODES];
__device__ __align__(16) float g_h  [N_NODES * 64];   // GEMM output of current layer
__device__ __align__(16) float g_agg[N_NODES * 64];   // scatter accumulator
__device__ __align__(16) float g_x1 [N_NODES * 64];   // layer-1 activation
__device__ __align__(16) float g_x2 [N_NODES * 64];   // layer-2 activation
__device__ int   g_src[N_EDGES];
__device__ int   g_dst[N_EDGES];
__device__ float g_w  [N_EDGES];

// ---------------- norm precompute ----------------------------------------------
__global__ void k_init_deg(float* dinv) {
    int i = blockIdx.x * blockDim.x + threadIdx.x;
    if (i < N_NODES) dinv[i] = 1.0f;  // self-loop contributes 1 to every degree
}

__global__ void k_count_deg(const int* __restrict__ ei, float* dinv) {
    int e = blockIdx.x * blockDim.x + threadIdx.x;
    if (e < N_EDGES) atomicAdd(&dinv[ei[N_EDGES + e]], 1.0f);
}

__global__ void k_finish_dinv(float* dinv) {
    int i = blockIdx.x * blockDim.x + threadIdx.x;
    if (i < N_NODES) dinv[i] = rsqrtf(dinv[i]);
}

__global__ void k_prep_edges(const int* __restrict__ ei,
                             const float* __restrict__ dinv,
                             int* __restrict__ src, int* __restrict__ dst,
                             float* __restrict__ w) {
    int e = blockIdx.x * blockDim.x + threadIdx.x;
    if (e >= N_EDGES) return;
    int s = ei[e];
    int d = ei[N_EDGES + e];
    src[e] = s;
    dst[e] = d;
    w[e]   = dinv[s] * dinv[d];
}

// ---------------- small GEMM: H[N, DOUT] = X[N, 64] @ W[64, DOUT] ---------------
template <int DOUT>
__global__ void k_gemm(const float* __restrict__ X, const float* __restrict__ W,
                       float* __restrict__ H) {
    constexpr int DIN  = 64;
    constexpr int ROWS = 32;
    constexpr int G    = 256 / DOUT;  // row groups per block
    __shared__ float sW[DIN * DOUT];
    __shared__ float sX[ROWS * DIN];

    int tid = threadIdx.x;
    for (int i = tid; i < DIN * DOUT; i += 256) sW[i] = W[i];

    int rowbase = blockIdx.x * ROWS;
    for (int i = tid; i < ROWS * DIN; i += 256) {
        int row = rowbase + i / DIN;
        sX[i] = (row < N_NODES) ? X[(size_t)row * DIN + (i % DIN)] : 0.0f;
    }
    __syncthreads();

    int col = tid % DOUT;
    int grp = tid / DOUT;
    for (int r = grp; r < ROWS; r += G) {
        int row = rowbase + r;
        if (row >= N_NODES) break;
        float acc = 0.0f;
#pragma unroll
        for (int k = 0; k < DIN; k++)
            acc = fmaf(sX[r * DIN + k], sW[k * DOUT + col], acc);
        H[(size_t)row * DOUT + col] = acc;
    }
}

// ---------------- zero the accumulator -----------------------------------------
__global__ void k_zero(float4* __restrict__ p, int n4) {
    int i = blockIdx.x * blockDim.x + threadIdx.x;
    if (i < n4) p[i] = make_float4(0.f, 0.f, 0.f, 0.f);
}

// ---------------- edge scatter: agg[dst] += h[src] * w --------------------------
template <int DOUT>
__global__ void k_scatter(const int* __restrict__ src, const int* __restrict__ dst,
                          const float* __restrict__ w,
                          const float* __restrict__ H, float* __restrict__ AGG) {
    constexpr int C = DOUT / 4;  // float4 chunks per edge
    long long t = (long long)blockIdx.x * blockDim.x + threadIdx.x;
    if (t >= (long long)N_EDGES * C) return;
    int e = (int)(t / C);
    int c = (int)(t % C);
    int s = src[e];
    int d = dst[e];
    float wv = w[e];
    float4 v = ((const float4*)H)[(size_t)s * C + c];
    float* base = &AGG[(size_t)d * DOUT + 4 * c];
    atomicAdd(base + 0, v.x * wv);
    atomicAdd(base + 1, v.y * wv);
    atomicAdd(base + 2, v.z * wv);
    atomicAdd(base + 3, v.w * wv);
}

// ---------------- epilogue: out = act(agg + h * dinv^2 + b) ---------------------
template <int DOUT, bool TANH>
__global__ void k_epilogue(const float* __restrict__ AGG, const float* __restrict__ H,
                           const float* __restrict__ dinv, const float* __restrict__ b,
                           float* __restrict__ OUT) {
    constexpr int C = DOUT / 4;
    int i = blockIdx.x * blockDim.x + threadIdx.x;
    if (i >= N_NODES * C) return;
    int node = i / C;
    int j    = i % C;
    float di = dinv[node];
    float sl = di * di;  // self-loop norm
    float4 a  = ((const float4*)AGG)[i];
    float4 h  = ((const float4*)H)[i];
    float4 bb = ((const float4*)b)[j];
    float4 v;
    v.x = a.x + h.x * sl + bb.x;
    v.y = a.y + h.y * sl + bb.y;
    v.z = a.z + h.z * sl + bb.z;
    v.w = a.w + h.w * sl + bb.w;
    if (TANH) {
        v.x = tanhf(v.x); v.y = tanhf(v.y); v.z = tanhf(v.z); v.w = tanhf(v.w);
    }
    ((float4*)OUT)[i] = v;
}

// ---------------- launch --------------------------------------------------------
static inline int cdiv(long long a, int b) { return (int)((a + b - 1) / b); }

extern "C" void kernel_launch(void* const* d_in, const int* in_sizes, int n_in,
                              void* d_out, int out_size) {
    const float* x  = (const float*)d_in[0];
    const int*   ei = (const int*)d_in[1];      // JAX x64 disabled: int64 -> int32
    const float* W1 = (const float*)d_in[2];
    const float* b1 = (const float*)d_in[3];
    const float* W2 = (const float*)d_in[4];
    const float* b2 = (const float*)d_in[5];
    const float* W3 = (const float*)d_in[6];
    const float* b3 = (const float*)d_in[7];
    float*       out = (float*)d_out;

    // Resolve device-global scratch addresses (no allocation; just symbol lookup).
    float *dinv, *h, *agg, *x1, *x2, *w;
    int   *src, *dst;
    cudaGetSymbolAddress((void**)&dinv, g_dinv);
    cudaGetSymbolAddress((void**)&h,    g_h);
    cudaGetSymbolAddress((void**)&agg,  g_agg);
    cudaGetSymbolAddress((void**)&x1,   g_x1);
    cudaGetSymbolAddress((void**)&x2,   g_x2);
    cudaGetSymbolAddress((void**)&src,  g_src);
    cudaGetSymbolAddress((void**)&dst,  g_dst);
    cudaGetSymbolAddress((void**)&w,    g_w);

    const int T = 256;

    // ---- norm precompute ----
    k_init_deg   <<<cdiv(N_NODES, T), T>>>(dinv);
    k_count_deg  <<<cdiv(N_EDGES, T), T>>>(ei, dinv);
    k_finish_dinv<<<cdiv(N_NODES, T), T>>>(dinv);
    k_prep_edges <<<cdiv(N_EDGES, T), T>>>(ei, dinv, src, dst, w);

    // ---- layer 1: x -> x1 (tanh) ----
    k_gemm<64><<<cdiv(N_NODES, 32), T>>>(x, W1, h);
    k_zero<<<cdiv(N_NODES * 16, T), T>>>((float4*)agg, N_NODES * 16);
    k_scatter<64><<<cdiv((long long)N_EDGES * 16, T), T>>>(src, dst, w, h, agg);
    k_epilogue<64, true><<<cdiv(N_NODES * 16, T), T>>>(agg, h, dinv, b1, x1);

    // ---- layer 2: x1 -> x2 (tanh) ----
    k_gemm<64><<<cdiv(N_NODES, 32), T>>>(x1, W2, h);
    k_zero<<<cdiv(N_NODES * 16, T), T>>>((float4*)agg, N_NODES * 16);
    k_scatter<64><<<cdiv((long long)N_EDGES * 16, T), T>>>(src, dst, w, h, agg);
    k_epilogue<64, true><<<cdiv(N_NODES * 16, T), T>>>(agg, h, dinv, b2, x2);

    // ---- layer 3: x2 -> out (linear) ----
    k_gemm<32><<<cdiv(N_NODES, 32), T>>>(x2, W3, h);
    k_zero<<<cdiv(N_NODES * 8, T), T>>>((float4*)agg, N_NODES * 8);
    k_scatter<32><<<cdiv((long long)N_EDGES * 8, T), T>>>(src, dst, w, h, agg);
    k_epilogue<32, false><<<cdiv(N_NODES * 8, T), T>>>(agg, h, dinv, b3, out);
}

// round 4
// speedup vs baseline: 2.0710x; 2.0710x over previous
#include <cuda_runtime.h>
#include <cstdint>

#define N_NODES 50000
#define N_EDGES 800000
#define NB_SCAN 196          // ceil(50000/256)

// ---------------- device scratch (allocation-free rule: __device__ globals) ----
__device__ __align__(16) float g_dinv[N_NODES];
__device__ __align__(16) float g_h  [N_NODES * 64];   // GEMM output of current layer
__device__ __align__(16) float g_x1 [N_NODES * 64];   // layer-1 activation
__device__ __align__(16) float g_x2 [N_NODES * 64];   // layer-2 activation
__device__ int   g_deg [N_NODES];
__device__ int   g_ptr [N_NODES + 1];
__device__ int   g_fill[N_NODES];
__device__ int   g_bsum[NB_SCAN];
__device__ int   g_csr_src[N_EDGES];
__device__ float g_csr_w  [N_EDGES];

// ---------------- degree + norm ------------------------------------------------
__global__ void k_init_deg(int* deg) {
    int i = blockIdx.x * blockDim.x + threadIdx.x;
    if (i < N_NODES) deg[i] = 0;
}

__global__ void k_count_deg(const int* __restrict__ ei, int* deg) {
    int e = blockIdx.x * blockDim.x + threadIdx.x;
    if (e < N_EDGES) atomicAdd(&deg[ei[N_EDGES + e]], 1);
}

__global__ void k_dinv(const int* __restrict__ deg, float* dinv) {
    int i = blockIdx.x * blockDim.x + threadIdx.x;
    if (i < N_NODES) dinv[i] = rsqrtf((float)deg[i] + 1.0f);  // +1 self-loop
}

// ---------------- 3-kernel exclusive scan of deg -> ptr ------------------------
__global__ void k_scanA(const int* __restrict__ deg, int* __restrict__ bsum) {
    __shared__ int s[256];
    int t = threadIdx.x;
    int i = blockIdx.x * 256 + t;
    s[t] = (i < N_NODES) ? deg[i] : 0;
    __syncthreads();
    for (int o = 128; o > 0; o >>= 1) {
        if (t < o) s[t] += s[t + o];
        __syncthreads();
    }
    if (t == 0) bsum[blockIdx.x] = s[0];
}

__global__ void k_scanB(int* bsum) {
    __shared__ int s[256];
    int t = threadIdx.x;
    int v = (t < NB_SCAN) ? bsum[t] : 0;
    s[t] = v;
    __syncthreads();
    for (int o = 1; o < 256; o <<= 1) {
        int u = (t >= o) ? s[t - o] : 0;
        __syncthreads();
        s[t] += u;
        __syncthreads();
    }
    if (t < NB_SCAN) bsum[t] = s[t] - v;  // exclusive
}

__global__ void k_scanC(const int* __restrict__ deg, const int* __restrict__ bsum,
                        int* __restrict__ ptr, int* __restrict__ fill) {
    __shared__ int s[256];
    int t = threadIdx.x;
    int i = blockIdx.x * 256 + t;
    int v = (i < N_NODES) ? deg[i] : 0;
    s[t] = v;
    __syncthreads();
    for (int o = 1; o < 256; o <<= 1) {
        int u = (t >= o) ? s[t - o] : 0;
        __syncthreads();
        s[t] += u;
        __syncthreads();
    }
    int excl = s[t] - v + bsum[blockIdx.x];
    if (i < N_NODES) { ptr[i] = excl; fill[i] = excl; }
    if (i == N_NODES) ptr[N_NODES] = N_EDGES;
}

// ---------------- counting-sort fill: CSR by dst --------------------------------
__global__ void k_fill(const int* __restrict__ ei, const float* __restrict__ dinv,
                       int* fill, int* __restrict__ csr_src, float* __restrict__ csr_w) {
    int e = blockIdx.x * blockDim.x + threadIdx.x;
    if (e >= N_EDGES) return;
    int s = ei[e];
    int d = ei[N_EDGES + e];
    int pos = atomicAdd(&fill[d], 1);
    csr_src[pos] = s;
    csr_w[pos]   = dinv[s] * dinv[d];
}

// ---------------- small GEMM: H[N, DOUT] = X[N, 64] @ W[64, DOUT] ---------------
template <int DOUT>
__global__ void k_gemm(const float* __restrict__ X, const float* __restrict__ W,
                       float* __restrict__ H) {
    constexpr int DIN  = 64;
    constexpr int ROWS = 32;
    constexpr int G    = 256 / DOUT;
    __shared__ float sW[DIN * DOUT];
    __shared__ float sX[ROWS * DIN];

    int tid = threadIdx.x;
    for (int i = tid; i < DIN * DOUT; i += 256) sW[i] = W[i];

    int rowbase = blockIdx.x * ROWS;
    for (int i = tid; i < ROWS * DIN; i += 256) {
        int row = rowbase + i / DIN;
        sX[i] = (row < N_NODES) ? X[(size_t)row * DIN + (i % DIN)] : 0.0f;
    }
    __syncthreads();

    int col = tid % DOUT;
    int grp = tid / DOUT;
    for (int r = grp; r < ROWS; r += G) {
        int row = rowbase + r;
        if (row >= N_NODES) break;
        float acc = 0.0f;
#pragma unroll
        for (int k = 0; k < DIN; k++)
            acc = fmaf(sX[r * DIN + k], sW[k * DOUT + col], acc);
        H[(size_t)row * DOUT + col] = acc;
    }
}

// ---- fused pull aggregation + self-loop + bias + activation --------------------
// C = DOUT/4 threads per node, each owning one float4 lane.
template <int DOUT, bool TANH>
__global__ void k_agg(const int* __restrict__ ptr, const int* __restrict__ csr_src,
                      const float* __restrict__ csr_w,
                      const float* __restrict__ H, const float* __restrict__ dinv,
                      const float* __restrict__ b, float* __restrict__ OUT) {
    constexpr int C   = DOUT / 4;     // 16 (d=64) or 8 (d=32)
    constexpr int NPB = 256 / C;      // nodes per block
    int lane = threadIdx.x % C;
    int node = blockIdx.x * NPB + threadIdx.x / C;
    if (node >= N_NODES) return;

    int beg = ptr[node];
    int end = ptr[node + 1];
    const float4* H4 = (const float4*)H;

    float4 acc = make_float4(0.f, 0.f, 0.f, 0.f);
    int e = beg;
    // 2-deep software pipeline for memory-level parallelism
    for (; e + 1 < end; e += 2) {
        int    s0 = csr_src[e],     s1 = csr_src[e + 1];
        float  w0 = csr_w[e],       w1 = csr_w[e + 1];
        float4 v0 = H4[(size_t)s0 * C + lane];
        float4 v1 = H4[(size_t)s1 * C + lane];
        acc.x += v0.x * w0 + v1.x * w1;
        acc.y += v0.y * w0 + v1.y * w1;
        acc.z += v0.z * w0 + v1.z * w1;
        acc.w += v0.w * w0 + v1.w * w1;
    }
    if (e < end) {
        int    s0 = csr_src[e];
        float  w0 = csr_w[e];
        float4 v0 = H4[(size_t)s0 * C + lane];
        acc.x += v0.x * w0;
        acc.y += v0.y * w0;
        acc.z += v0.z * w0;
        acc.w += v0.w * w0;
    }

    float di = dinv[node];
    float sl = di * di;                       // self-loop weight
    float4 hh = H4[(size_t)node * C + lane];
    float4 bb = ((const float4*)b)[lane];
    float4 v;
    v.x = acc.x + hh.x * sl + bb.x;
    v.y = acc.y + hh.y * sl + bb.y;
    v.z = acc.z + hh.z * sl + bb.z;
    v.w = acc.w + hh.w * sl + bb.w;
    if (TANH) {
        v.x = tanhf(v.x); v.y = tanhf(v.y); v.z = tanhf(v.z); v.w = tanhf(v.w);
    }
    ((float4*)OUT)[(size_t)node * C + lane] = v;
}

// ---------------- launch --------------------------------------------------------
static inline int cdiv(long long a, int b) { return (int)((a + b - 1) / b); }

extern "C" void kernel_launch(void* const* d_in, const int* in_sizes, int n_in,
                              void* d_out, int out_size) {
    const float* x  = (const float*)d_in[0];
    const int*   ei = (const int*)d_in[1];      // JAX x64 disabled: int64 -> int32
    const float* W1 = (const float*)d_in[2];
    const float* b1 = (const float*)d_in[3];
    const float* W2 = (const float*)d_in[4];
    const float* b2 = (const float*)d_in[5];
    const float* W3 = (const float*)d_in[6];
    const float* b3 = (const float*)d_in[7];
    float*       out = (float*)d_out;

    float *dinv, *h, *x1, *x2, *csr_w;
    int   *deg, *ptr, *fill, *bsum, *csr_src;
    cudaGetSymbolAddress((void**)&dinv,    g_dinv);
    cudaGetSymbolAddress((void**)&h,       g_h);
    cudaGetSymbolAddress((void**)&x1,      g_x1);
    cudaGetSymbolAddress((void**)&x2,      g_x2);
    cudaGetSymbolAddress((void**)&deg,     g_deg);
    cudaGetSymbolAddress((void**)&ptr,     g_ptr);
    cudaGetSymbolAddress((void**)&fill,    g_fill);
    cudaGetSymbolAddress((void**)&bsum,    g_bsum);
    cudaGetSymbolAddress((void**)&csr_src, g_csr_src);
    cudaGetSymbolAddress((void**)&csr_w,   g_csr_w);

    const int T = 256;

    // ---- CSR build + norm ----
    k_init_deg <<<cdiv(N_NODES, T), T>>>(deg);
    k_count_deg<<<cdiv(N_EDGES, T), T>>>(ei, deg);
    k_dinv     <<<cdiv(N_NODES, T), T>>>(deg, dinv);
    k_scanA    <<<NB_SCAN, T>>>(deg, bsum);
    k_scanB    <<<1, T>>>(bsum);
    k_scanC    <<<NB_SCAN, T>>>(deg, bsum, ptr, fill);
    k_fill     <<<cdiv(N_EDGES, T), T>>>(ei, dinv, fill, csr_src, csr_w);

    // ---- layer 1: x -> x1 (tanh) ----
    k_gemm<64><<<cdiv(N_NODES, 32), T>>>(x, W1, h);
    k_agg<64, true><<<cdiv(N_NODES * 16, T), T>>>(ptr, csr_src, csr_w, h, dinv, b1, x1);

    // ---- layer 2: x1 -> x2 (tanh) ----
    k_gemm<64><<<cdiv(N_NODES, 32), T>>>(x1, W2, h);
    k_agg<64, true><<<cdiv(N_NODES * 16, T), T>>>(ptr, csr_src, csr_w, h, dinv, b2, x2);

    // ---- layer 3: x2 -> out (linear) ----
    k_gemm<32><<<cdiv(N_NODES, 32), T>>>(x2, W3, h);
    k_agg<32, false><<<cdiv(N_NODES * 8, T), T>>>(ptr, csr_src, csr_w, h, dinv, b3, out);
}